// round 10
// baseline (speedup 1.0000x reference)
#include <cuda_runtime.h>
#include <cuda_fp16.h>
#include <cstdint>

#define BATCH   2
#define NSEQ    2048
#define DMODEL  2048
#define INNERD  2048
#define EQKV    6144
#define NHEADS  16
#define HDIM    128
#define WINDOW  512
#define N_TOK   (BATCH * NSEQ)   // 4096
#define NHTOT   (BATCH * NHEADS * NSEQ * HDIM)   // 8.4M

typedef unsigned long long ull;

// ---------------- scratch (__device__ globals) ----------------
__device__ float g_qkv[N_TOK * EQKV];                    // fp32 qkv
__device__ __align__(16) __half g_xh[N_TOK * DMODEL];    // x fp16
__device__ __align__(16) __half g_wq[EQKV * DMODEL];     // w_qkv fp16
__device__ __align__(16) __half g_wo[DMODEL * INNERD];   // w_o fp16
__device__ __align__(16) __half g_ah[N_TOK * INNERD];    // attn out fp16
// head-major roped q/k/v, fp16 hi/lo (attention stays 3-term):
__device__ __align__(16) __half g_qh[NHTOT];
__device__ __align__(16) __half g_ql[NHTOT];
__device__ __align__(16) __half g_kh[NHTOT];
__device__ __align__(16) __half g_kl[NHTOT];
__device__ __align__(16) __half g_vh[NHTOT];
__device__ __align__(16) __half g_vl[NHTOT];

// ---------------- PTX helpers (baseline ISA only) ----------------
__device__ __forceinline__ uint32_t smem_u32(const void* p) {
    uint32_t a;
    asm("{ .reg .u64 t; cvta.to.shared.u64 t, %1; cvt.u32.u64 %0, t; }"
        : "=r"(a) : "l"(p));
    return a;
}
__device__ __forceinline__ void cp16(uint32_t dst, const void* src) {
    asm volatile("cp.async.cg.shared.global [%0], [%1], 16;" :: "r"(dst), "l"(src));
}
__device__ __forceinline__ void cp_commit() {
    asm volatile("cp.async.commit_group;" ::: "memory");
}
__device__ __forceinline__ void ldsm_x4(uint32_t* r, uint32_t addr) {
    asm volatile("ldmatrix.sync.aligned.m8n8.x4.shared.b16 {%0,%1,%2,%3}, [%4];"
                 : "=r"(r[0]), "=r"(r[1]), "=r"(r[2]), "=r"(r[3]) : "r"(addr));
}
__device__ __forceinline__ void ldsm_x2(uint32_t* r, uint32_t addr) {
    asm volatile("ldmatrix.sync.aligned.m8n8.x2.shared.b16 {%0,%1}, [%2];"
                 : "=r"(r[0]), "=r"(r[1]) : "r"(addr));
}
__device__ __forceinline__ void ldsm_x4t(uint32_t* r, uint32_t addr) {
    asm volatile("ldmatrix.sync.aligned.m8n8.x4.trans.shared.b16 {%0,%1,%2,%3}, [%4];"
                 : "=r"(r[0]), "=r"(r[1]), "=r"(r[2]), "=r"(r[3]) : "r"(addr));
}
__device__ __forceinline__ void mma16816(float* c, const uint32_t* a, const uint32_t* b) {
    asm volatile("mma.sync.aligned.m16n8k16.row.col.f32.f16.f16.f32 "
                 "{%0,%1,%2,%3}, {%4,%5,%6,%7}, {%8,%9}, {%0,%1,%2,%3};"
                 : "+f"(c[0]), "+f"(c[1]), "+f"(c[2]), "+f"(c[3])
                 : "r"(a[0]), "r"(a[1]), "r"(a[2]), "r"(a[3]),
                   "r"(b[0]), "r"(b[1]));
}
__device__ __forceinline__ void splith(float x, __half& h, __half& l) {
    h = __float2half_rn(x);
    l = __float2half_rn(x - __half2float(h));
}
__device__ __forceinline__ uint32_t pack2(__half a, __half b) {
    __half2 t = __halves2half2(a, b);
    return *(uint32_t*)&t;
}

// ---------------- fp32 -> fp16 round ----------------
__global__ void conv_f16(const float4* __restrict__ in,
                         __half2* __restrict__ out, int n4) {
    int i = blockIdx.x * blockDim.x + threadIdx.x;
    if (i >= n4) return;
    float4 v = in[i];
    out[i * 2]     = __halves2half2(__float2half_rn(v.x), __float2half_rn(v.y));
    out[i * 2 + 1] = __halves2half2(__float2half_rn(v.z), __float2half_rn(v.w));
}

// ---------------- mma.sync fp16 NT GEMM (single-term) ----------------
// C[M,N] = A[M,K] * B[N,K]^T in fp32, A and B fp16.
// CTA: 128x128 tile, BK=32, 256 threads (8 warps = 2m x 4n), 64x32 per warp.
// SMEM stage (16 KB): A at +0: [kc][row][32B]; B at +8192: same.
#define GEMM_STAGE   16384
#define GEMM_NSTAGE  3
#define GEMM_SMEM_BYTES (GEMM_NSTAGE * GEMM_STAGE)   // 49152

__device__ __forceinline__ void load_stage_body(
    uint32_t st, const __half* __restrict__ A, const __half* __restrict__ B,
    long tm, long tn, int k0, int K, int tid)
{
    #pragma unroll
    for (int it = 0; it < 4; it++) {
        int s = tid + it * 256;          // 0..1023
        int mat = s >> 9;                // 0=A, 1=B
        int r  = (s >> 2) & 127;
        int q  = s & 3;
        const __half* src = mat ? B : A;
        long row = (mat ? tn : tm) + r;
        uint32_t dst = st + mat * 8192 + (q >> 1) * 4096 + r * 32 + (q & 1) * 16;
        cp16(dst, src + row * (long)K + k0 + q * 8);
    }
}

__global__ __launch_bounds__(256, 2) void gemm_tc(
    const __half* __restrict__ A, const __half* __restrict__ B,
    float* __restrict__ C, int Nn, int K)
{
    extern __shared__ char dynsmem[];
    uint32_t st0 = smem_u32(dynsmem);

    int tid  = threadIdx.x;
    int lane = tid & 31;
    int wid  = tid >> 5;
    int wm   = (wid >> 2) * 64;
    int wn   = (wid & 3) * 32;

    long tm = (long)blockIdx.y * 128;
    long tn = (long)blockIdx.x * 128;
    int NC = K / 32;

    uint32_t aOff = (uint32_t)((wm + (lane & 15)) * 32 + (lane >> 4) * 16);
    uint32_t bOff = (uint32_t)((wn + (lane & 7)) * 32 + ((lane >> 3) & 1) * 16);

    float acc[4][4][4];
    #pragma unroll
    for (int mi = 0; mi < 4; mi++)
        #pragma unroll
        for (int ni = 0; ni < 4; ni++)
            #pragma unroll
            for (int q = 0; q < 4; q++) acc[mi][ni][q] = 0.f;

    load_stage_body(st0, A, B, tm, tn, 0, K, tid);
    cp_commit();
    if (NC > 1) load_stage_body(st0 + GEMM_STAGE, A, B, tm, tn, 32, K, tid);
    cp_commit();

    int stg = 0, stg2 = 2;
    for (int c = 0; c < NC; c++) {
        asm volatile("cp.async.wait_group 1;" ::: "memory");
        __syncthreads();

        if (c + 2 < NC)
            load_stage_body(st0 + stg2 * GEMM_STAGE, A, B,
                            tm, tn, (c + 2) * 32, K, tid);
        cp_commit();

        uint32_t sa = st0 + stg * GEMM_STAGE;

        #pragma unroll
        for (int kc = 0; kc < 2; kc++) {
            uint32_t ab = sa + kc * 4096 + aOff;
            uint32_t bb = sa + 8192 + kc * 4096 + bOff;

            uint32_t aH[4][4], bH[4][2];
            #pragma unroll
            for (int mi = 0; mi < 4; mi++)
                ldsm_x4(aH[mi], ab + mi * 512);
            #pragma unroll
            for (int ni = 0; ni < 4; ni++)
                ldsm_x2(bH[ni], bb + ni * 256);

            #pragma unroll
            for (int mi = 0; mi < 4; mi++)
                #pragma unroll
                for (int ni = 0; ni < 4; ni++)
                    mma16816(acc[mi][ni], aH[mi], bH[ni]);
        }

        stg  = (stg  + 1 == GEMM_NSTAGE) ? 0 : stg + 1;
        stg2 = (stg2 + 1 == GEMM_NSTAGE) ? 0 : stg2 + 1;
    }

    int r0 = (lane >> 2);
    int c0 = (lane & 3) * 2;
    #pragma unroll
    for (int mi = 0; mi < 4; mi++) {
        long row = tm + wm + mi * 16 + r0;
        #pragma unroll
        for (int ni = 0; ni < 4; ni++) {
            long col = tn + wn + ni * 8 + c0;
            *(float2*)&C[row * (long)Nn + col] =
                make_float2(acc[mi][ni][0], acc[mi][ni][1]);
            *(float2*)&C[(row + 8) * (long)Nn + col] =
                make_float2(acc[mi][ni][2], acc[mi][ni][3]);
        }
    }
}

// ---------------- RoPE + head-major fp16 hi/lo split ----------------
__global__ void rope_split() {
    int idx = blockIdx.x * blockDim.x + threadIdx.x;
    if (idx >= N_TOK * 64) return;
    int d = idx & 63;
    int m = idx >> 6;
    int n = m & (NSEQ - 1);
    int b = m >> 11;

    double inv = exp(-(double)d * (9.210340371976184 / 64.0));
    double ang = (double)n * inv;
    const double TWO_PI = 6.283185307179586476925286766559;
    double w = ang - floor(ang / TWO_PI) * TWO_PI;
    float c = cosf((float)w);
    float s = sinf((float)w);
    const float scale = 0.088388347648318447f;   // 1/sqrt(128)

    const float* base = g_qkv + (long)m * EQKV;
    #pragma unroll
    for (int h = 0; h < NHEADS; h++) {
        const float* q = base + h * HDIM;
        const float* k = q + INNERD;
        const float* v = k + INNERD;
        float q1 = q[d], q2 = q[d + 64];
        float k1 = k[d], k2 = k[d + 64];
        float v1 = v[d], v2 = v[d + 64];
        float qr1 = (q1 * c - q2 * s) * scale;
        float qr2 = (q2 * c + q1 * s) * scale;
        float kr1 = k1 * c - k2 * s;
        float kr2 = k2 * c + k1 * s;

        long o = ((long)(b * NHEADS + h) * NSEQ + n) * HDIM;
        __half hh, ll;
        splith(qr1, hh, ll); g_qh[o + d] = hh;      g_ql[o + d] = ll;
        splith(qr2, hh, ll); g_qh[o + d + 64] = hh; g_ql[o + d + 64] = ll;
        splith(kr1, hh, ll); g_kh[o + d] = hh;      g_kl[o + d] = ll;
        splith(kr2, hh, ll); g_kh[o + d + 64] = hh; g_kl[o + d + 64] = ll;
        splith(v1,  hh, ll); g_vh[o + d] = hh;      g_vl[o + d] = ll;
        splith(v2,  hh, ll); g_vh[o + d + 64] = hh; g_vl[o + d + 64] = ll;
    }
}

// ---------------- HMMA flash attention (3-term hi/lo, unchanged core) ------
#define AQ 128
#define SQ_BYTES 32768
#define SK_BYTES 16384
#define ASTAGE   (4 * SK_BYTES)                     // 64KB
#define ATTN_SMEM_BYTES (2 * SQ_BYTES + 2 * ASTAGE) // 192KB

__device__ __forceinline__ void load_q(uint32_t sQh, uint32_t sQl,
                                       const __half* qh, const __half* ql, int tid) {
    #pragma unroll
    for (int it = 0; it < 16; it++) {
        int s = tid + it * 256;
        int mat = s >> 11;
        int r = (s >> 4) & 127;
        int q = s & 15;
        uint32_t dst = (mat ? sQl : sQh) + (q >> 1) * 4096 + r * 32 + (q & 1) * 16;
        cp16(dst, (mat ? ql : qh) + r * 128 + q * 8);
    }
}

__device__ __forceinline__ void load_kv(uint32_t st,
                                        const __half* kh, const __half* kl,
                                        const __half* vh, const __half* vl, int tid) {
    #pragma unroll
    for (int it = 0; it < 16; it++) {
        int s = tid + it * 256;
        int mat = s >> 10;
        int r = (s >> 4) & 63;
        int q = s & 15;
        const __half* src = (mat == 0) ? kh : (mat == 1) ? kl : (mat == 2) ? vh : vl;
        uint32_t dst = st + mat * SK_BYTES + (q >> 1) * 2048 + r * 32 + (q & 1) * 16;
        cp16(dst, src + r * 128 + q * 8);
    }
}

__global__ __launch_bounds__(256, 1) void attn_tc() {
    extern __shared__ char dynsmem[];
    uint32_t sb  = smem_u32(dynsmem);
    uint32_t sQh = sb;
    uint32_t sQl = sb + SQ_BYTES;
    uint32_t st0 = sb + 2 * SQ_BYTES;

    int tid  = threadIdx.x;
    int lane = tid & 31;
    int wid  = tid >> 5;
    int qb   = blockIdx.x;
    int h    = blockIdx.y;
    int b    = blockIdx.z;
    int qs   = qb * AQ;

    long hb = (long)(b * NHEADS + h) * NSEQ;
    const __half* qhg = g_qh + (hb + qs) * HDIM;
    const __half* qlg = g_ql + (hb + qs) * HDIM;

    int kt0 = (qs >= WINDOW) ? ((qs - WINDOW + 1) >> 6) : 0;
    int kt1 = (qs + AQ - 1) >> 6;

    load_q(sQh, sQl, qhg, qlg, tid);
    {
        int ks = kt0 * 64;
        load_kv(st0, g_kh + (hb + ks) * HDIM, g_kl + (hb + ks) * HDIM,
                g_vh + (hb + ks) * HDIM, g_vl + (hb + ks) * HDIM, tid);
    }
    cp_commit();
    if (kt0 + 1 <= kt1) {
        int ks = (kt0 + 1) * 64;
        load_kv(st0 + ASTAGE, g_kh + (hb + ks) * HDIM, g_kl + (hb + ks) * HDIM,
                g_vh + (hb + ks) * HDIM, g_vl + (hb + ks) * HDIM, tid);
    }
    cp_commit();

    int qw = qs + wid * 16;
    int r0 = lane >> 2;
    int cb = (lane & 3) * 2;

    uint32_t qOff = (uint32_t)((wid * 16 + (lane & 15)) * 32 + (lane >> 4) * 16);
    uint32_t kRow = (uint32_t)((lane & 7) + ((lane >> 4) << 3));
    uint32_t kHlf = (uint32_t)(((lane >> 3) & 1) * 16);
    uint32_t vOff = (uint32_t)((lane & 15) * 32 + (lane >> 4) * 16);

    float mrow[2], lrow[2];
    float oacc[16][4];
    mrow[0] = mrow[1] = -1e30f;
    lrow[0] = lrow[1] = 0.f;
    #pragma unroll
    for (int nt = 0; nt < 16; nt++)
        #pragma unroll
        for (int q = 0; q < 4; q++) oacc[nt][q] = 0.f;

    for (int kt = kt0; kt <= kt1; kt++) {
        int st = (kt - kt0) & 1;
        asm volatile("cp.async.wait_group 1;" ::: "memory");
        __syncthreads();

        int ks = kt * 64;
        uint32_t S  = st0 + st * ASTAGE;
        uint32_t kh_ = S, kl_ = S + SK_BYTES;
        uint32_t vh_ = S + 2 * SK_BYTES, vl_ = S + 3 * SK_BYTES;

        bool active = (ks <= qw + 15) && (ks + 63 > qw - WINDOW);

        if (active) {
            float sacc[8][4];
            #pragma unroll
            for (int nt = 0; nt < 8; nt++)
                #pragma unroll
                for (int q = 0; q < 4; q++) sacc[nt][q] = 0.f;

            #pragma unroll
            for (int c = 0; c < 8; c++) {
                uint32_t aH[4], aL[4];
                ldsm_x4(aH, sQh + c * 4096 + qOff);
                ldsm_x4(aL, sQl + c * 4096 + qOff);
                #pragma unroll
                for (int p = 0; p < 4; p++) {
                    uint32_t addr = (p * 16 + kRow) * 32 + kHlf + c * 2048;
                    uint32_t bh[4], bl[4];
                    ldsm_x4(bh, kh_ + addr);
                    ldsm_x4(bl, kl_ + addr);
                    mma16816(sacc[2 * p],     aH, bh);
                    mma16816(sacc[2 * p],     aH, bl);
                    mma16816(sacc[2 * p],     aL, bh);
                    mma16816(sacc[2 * p + 1], aH, bh + 2);
                    mma16816(sacc[2 * p + 1], aH, bl + 2);
                    mma16816(sacc[2 * p + 1], aL, bh + 2);
                }
            }

            #pragma unroll
            for (int hf = 0; hf < 2; hf++) {
                int qi = qw + r0 + hf * 8;
                float mx = -1e30f;
                #pragma unroll
                for (int nt = 0; nt < 8; nt++) {
                    int kj0 = ks + nt * 8 + cb;
                    float v0 = sacc[nt][hf * 2], v1 = sacc[nt][hf * 2 + 1];
                    if (kj0 > qi || kj0 <= qi - WINDOW) v0 = -1e30f;
                    if (kj0 + 1 > qi || kj0 + 1 <= qi - WINDOW) v1 = -1e30f;
                    sacc[nt][hf * 2] = v0; sacc[nt][hf * 2 + 1] = v1;
                    mx = fmaxf(mx, fmaxf(v0, v1));
                }
                mx = fmaxf(mx, __shfl_xor_sync(0xffffffffu, mx, 1));
                mx = fmaxf(mx, __shfl_xor_sync(0xffffffffu, mx, 2));
                float mnew  = fmaxf(mrow[hf], mx);
                float alpha = __expf(mrow[hf] - mnew);
                mrow[hf] = mnew;

                float rs = 0.f;
                #pragma unroll
                for (int nt = 0; nt < 8; nt++) {
                    float v0 = sacc[nt][hf * 2], v1 = sacc[nt][hf * 2 + 1];
                    float p0 = (v0 < -1e29f) ? 0.f : __expf(v0 - mnew);
                    float p1 = (v1 < -1e29f) ? 0.f : __expf(v1 - mnew);
                    sacc[nt][hf * 2] = p0; sacc[nt][hf * 2 + 1] = p1;
                    rs += p0 + p1;
                }
                rs += __shfl_xor_sync(0xffffffffu, rs, 1);
                rs += __shfl_xor_sync(0xffffffffu, rs, 2);
                lrow[hf] = lrow[hf] * alpha + rs;

                #pragma unroll
                for (int nt = 0; nt < 16; nt++) {
                    oacc[nt][hf * 2]     *= alpha;
                    oacc[nt][hf * 2 + 1] *= alpha;
                }
            }

            uint32_t aPh[4][4], aPl[4][4];
            #pragma unroll
            for (int t = 0; t < 4; t++) {
                #pragma unroll
                for (int j = 0; j < 4; j++) {
                    int nt = 2 * t + (j >> 1);
                    int q0 = (j & 1) * 2;
                    __half h0, l0, h1, l1;
                    splith(sacc[nt][q0],     h0, l0);
                    splith(sacc[nt][q0 + 1], h1, l1);
                    aPh[t][j] = pack2(h0, h1);
                    aPl[t][j] = pack2(l0, l1);
                }
            }

            #pragma unroll
            for (int t = 0; t < 4; t++) {
                #pragma unroll
                for (int cc = 0; cc < 8; cc++) {
                    uint32_t addr = cc * 2048 + t * 512 + vOff;
                    uint32_t vh[4], vl[4];
                    ldsm_x4t(vh, vh_ + addr);
                    ldsm_x4t(vl, vl_ + addr);
                    mma16816(oacc[2 * cc],     aPh[t], vh);
                    mma16816(oacc[2 * cc],     aPh[t], vl);
                    mma16816(oacc[2 * cc],     aPl[t], vh);
                    mma16816(oacc[2 * cc + 1], aPh[t], vh + 2);
                    mma16816(oacc[2 * cc + 1], aPh[t], vl + 2);
                    mma16816(oacc[2 * cc + 1], aPl[t], vh + 2);
                }
            }
        }

        __syncthreads();
        if (kt + 2 <= kt1) {
            int ks2 = (kt + 2) * 64;
            load_kv(st0 + st * ASTAGE,
                    g_kh + (hb + ks2) * HDIM, g_kl + (hb + ks2) * HDIM,
                    g_vh + (hb + ks2) * HDIM, g_vl + (hb + ks2) * HDIM, tid);
        }
        cp_commit();
    }

    // ---- epilogue: normalize, round to single fp16 at [tok][h*128+d] ----
    #pragma unroll
    for (int hf = 0; hf < 2; hf++) {
        float inv = 1.0f / lrow[hf];
        long tok = (long)b * NSEQ + qw + r0 + hf * 8;
        #pragma unroll
        for (int nt = 0; nt < 16; nt++) {
            int col = h * HDIM + nt * 8 + cb;
            float o0 = oacc[nt][hf * 2] * inv;
            float o1 = oacc[nt][hf * 2 + 1] * inv;
            *(__half2*)&g_ah[tok * INNERD + col] =
                __halves2half2(__float2half_rn(o0), __float2half_rn(o1));
        }
    }
}

// ---------------- launch ----------------
extern "C" void kernel_launch(void* const* d_in, const int* in_sizes, int n_in,
                              void* d_out, int out_size) {
    const float* x     = (const float*)d_in[0];
    const float* w_qkv = (const float*)d_in[1];
    const float* w_o   = (const float*)d_in[2];
    float* y = (float*)d_out;

    float* qkv = nullptr;
    __half *xh, *wq, *wo, *ah;
    cudaGetSymbolAddress((void**)&qkv, g_qkv);
    cudaGetSymbolAddress((void**)&xh,  g_xh);
    cudaGetSymbolAddress((void**)&wq,  g_wq);
    cudaGetSymbolAddress((void**)&wo,  g_wo);
    cudaGetSymbolAddress((void**)&ah,  g_ah);

    cudaFuncSetAttribute(gemm_tc,
                         cudaFuncAttributeMaxDynamicSharedMemorySize,
                         GEMM_SMEM_BYTES);
    cudaFuncSetAttribute(attn_tc,
                         cudaFuncAttributeMaxDynamicSharedMemorySize,
                         ATTN_SMEM_BYTES);

    // 1) round operands to fp16
    {
        int n4 = (N_TOK * DMODEL) / 4;
        conv_f16<<<n4 / 256, 256>>>((const float4*)x, (__half2*)xh, n4);
    }
    {
        int n4 = (EQKV * DMODEL) / 4;
        conv_f16<<<n4 / 256, 256>>>((const float4*)w_qkv, (__half2*)wq, n4);
    }
    {
        int n4 = (DMODEL * INNERD) / 4;
        conv_f16<<<n4 / 256, 256>>>((const float4*)w_o, (__half2*)wo, n4);
    }

    // 2) QKV projection -> g_qkv fp32
    gemm_tc<<<dim3(EQKV / 128, N_TOK / 128), 256, GEMM_SMEM_BYTES>>>(
        xh, wq, qkv, EQKV, DMODEL);

    // 3) RoPE + head-major fp16 hi/lo split
    rope_split<<<(N_TOK * 64) / 256, 256>>>();

    // 4) HMMA flash attention -> g_ah (fp16, [tok][inner])
    attn_tc<<<dim3(NSEQ / AQ, NHEADS, BATCH), 256, ATTN_SMEM_BYTES>>>();

    // 5) output projection -> y
    gemm_tc<<<dim3(DMODEL / 128, N_TOK / 128), 256, GEMM_SMEM_BYTES>>>(
        ah, wo, y, DMODEL, INNERD);
}

// round 11
// speedup vs baseline: 1.4886x; 1.4886x over previous
#include <cuda_runtime.h>
#include <cuda_fp16.h>
#include <cstdint>

#define BATCH   2
#define NSEQ    2048
#define DMODEL  2048
#define INNERD  2048
#define EQKV    6144
#define NHEADS  16
#define HDIM    128
#define WINDOW  512
#define N_TOK   (BATCH * NSEQ)   // 4096
#define NHTOT   (BATCH * NHEADS * NSEQ * HDIM)   // 8.4M

typedef unsigned long long ull;

// ---------------- scratch (__device__ globals) ----------------
__device__ float g_qkv[N_TOK * EQKV];                    // fp32 qkv
__device__ __align__(16) __half g_xh[N_TOK * DMODEL];    // x fp16
__device__ __align__(16) __half g_wq[EQKV * DMODEL];     // w_qkv fp16
__device__ __align__(16) __half g_wo[DMODEL * INNERD];   // w_o fp16
__device__ __align__(16) __half g_ah[N_TOK * INNERD];    // attn out fp16
// head-major roped q/k/v, fp16 hi/lo (attention stays 3-term):
__device__ __align__(16) __half g_qh[NHTOT];
__device__ __align__(16) __half g_ql[NHTOT];
__device__ __align__(16) __half g_kh[NHTOT];
__device__ __align__(16) __half g_kl[NHTOT];
__device__ __align__(16) __half g_vh[NHTOT];
__device__ __align__(16) __half g_vl[NHTOT];

// ---------------- PTX helpers (baseline ISA only) ----------------
__device__ __forceinline__ uint32_t smem_u32(const void* p) {
    uint32_t a;
    asm("{ .reg .u64 t; cvta.to.shared.u64 t, %1; cvt.u32.u64 %0, t; }"
        : "=r"(a) : "l"(p));
    return a;
}
__device__ __forceinline__ void cp16(uint32_t dst, const void* src) {
    asm volatile("cp.async.cg.shared.global [%0], [%1], 16;" :: "r"(dst), "l"(src));
}
__device__ __forceinline__ void cp_commit() {
    asm volatile("cp.async.commit_group;" ::: "memory");
}
__device__ __forceinline__ void ldsm_x4(uint32_t* r, uint32_t addr) {
    asm volatile("ldmatrix.sync.aligned.m8n8.x4.shared.b16 {%0,%1,%2,%3}, [%4];"
                 : "=r"(r[0]), "=r"(r[1]), "=r"(r[2]), "=r"(r[3]) : "r"(addr));
}
__device__ __forceinline__ void ldsm_x2(uint32_t* r, uint32_t addr) {
    asm volatile("ldmatrix.sync.aligned.m8n8.x2.shared.b16 {%0,%1}, [%2];"
                 : "=r"(r[0]), "=r"(r[1]) : "r"(addr));
}
__device__ __forceinline__ void ldsm_x4t(uint32_t* r, uint32_t addr) {
    asm volatile("ldmatrix.sync.aligned.m8n8.x4.trans.shared.b16 {%0,%1,%2,%3}, [%4];"
                 : "=r"(r[0]), "=r"(r[1]), "=r"(r[2]), "=r"(r[3]) : "r"(addr));
}
__device__ __forceinline__ void mma16816(float* c, const uint32_t* a, const uint32_t* b) {
    asm volatile("mma.sync.aligned.m16n8k16.row.col.f32.f16.f16.f32 "
                 "{%0,%1,%2,%3}, {%4,%5,%6,%7}, {%8,%9}, {%0,%1,%2,%3};"
                 : "+f"(c[0]), "+f"(c[1]), "+f"(c[2]), "+f"(c[3])
                 : "r"(a[0]), "r"(a[1]), "r"(a[2]), "r"(a[3]),
                   "r"(b[0]), "r"(b[1]));
}
__device__ __forceinline__ void splith(float x, __half& h, __half& l) {
    h = __float2half_rn(x);
    l = __float2half_rn(x - __half2float(h));
}
__device__ __forceinline__ uint32_t pack2(__half a, __half b) {
    __half2 t = __halves2half2(a, b);
    return *(uint32_t*)&t;
}

// ---------------- fp32 -> fp16 round ----------------
__global__ void conv_f16(const float4* __restrict__ in,
                         __half2* __restrict__ out, int n4) {
    int i = blockIdx.x * blockDim.x + threadIdx.x;
    if (i >= n4) return;
    float4 v = in[i];
    out[i * 2]     = __halves2half2(__float2half_rn(v.x), __float2half_rn(v.y));
    out[i * 2 + 1] = __halves2half2(__float2half_rn(v.z), __float2half_rn(v.w));
}

// ---------------- mma.sync fp16 NT GEMM (single-term, BK=64, pipelined) ----
// C[M,N] = A[M,K] * B[N,K]^T in fp32, A and B fp16.
// CTA: 128x128 tile, BK=64, 256 threads (8 warps = 2m x 4n), 64x32 per warp.
// SMEM stage (32 KB): A at +0: [kc0..3][row][32B]; B at +16384: same.
// 3 stages (96 KB/CTA), register double-buffered fragments across kc.
#define GEMM_STAGE   32768
#define GEMM_NSTAGE  3
#define GEMM_SMEM_BYTES (GEMM_NSTAGE * GEMM_STAGE)   // 98304

__device__ __forceinline__ void load_stage_body(
    uint32_t st, const __half* __restrict__ A, const __half* __restrict__ B,
    long tm, long tn, int k0, int K, int tid)
{
    #pragma unroll
    for (int it = 0; it < 8; it++) {
        int s = tid + it * 256;          // 0..2047
        int mat = s >> 10;               // 0=A, 1=B (1024 16B-segs each)
        int s2 = s & 1023;
        int r = s2 >> 3;                 // row 0..127
        int q = s2 & 7;                  // 16B quad within 128B k-row
        const __half* src = mat ? B : A;
        long row = (mat ? tn : tm) + r;
        uint32_t dst = st + mat * 16384 + (q >> 1) * 4096 + r * 32 + (q & 1) * 16;
        cp16(dst, src + row * (long)K + k0 + q * 8);
    }
}

__device__ __forceinline__ void ldfragA(uint32_t* f, uint32_t base) {
    #pragma unroll
    for (int mi = 0; mi < 4; mi++) ldsm_x4(f + mi * 4, base + mi * 512);
}
__device__ __forceinline__ void ldfragB(uint32_t* f, uint32_t base) {
    #pragma unroll
    for (int ni = 0; ni < 4; ni++) ldsm_x2(f + ni * 2, base + ni * 256);
}

__global__ __launch_bounds__(256, 2) void gemm_tc(
    const __half* __restrict__ A, const __half* __restrict__ B,
    float* __restrict__ C, int Nn, int K)
{
    extern __shared__ char dynsmem[];
    uint32_t st0 = smem_u32(dynsmem);

    int tid  = threadIdx.x;
    int lane = tid & 31;
    int wid  = tid >> 5;
    int wm   = (wid >> 2) * 64;
    int wn   = (wid & 3) * 32;

    long tm = (long)blockIdx.y * 128;
    long tn = (long)blockIdx.x * 128;
    int NC = K / 64;

    uint32_t aOff = (uint32_t)((wm + (lane & 15)) * 32 + (lane >> 4) * 16);
    uint32_t bOff = (uint32_t)((wn + (lane & 7)) * 32 + ((lane >> 3) & 1) * 16);

    float acc[4][4][4];
    #pragma unroll
    for (int mi = 0; mi < 4; mi++)
        #pragma unroll
        for (int ni = 0; ni < 4; ni++)
            #pragma unroll
            for (int q = 0; q < 4; q++) acc[mi][ni][q] = 0.f;

    load_stage_body(st0, A, B, tm, tn, 0, K, tid);
    cp_commit();
    load_stage_body(st0 + GEMM_STAGE, A, B, tm, tn, 64, K, tid);
    cp_commit();

    int stg = 0, stg2 = 2;
    for (int c = 0; c < NC; c++) {
        asm volatile("cp.async.wait_group 1;" ::: "memory");
        __syncthreads();

        if (c + 2 < NC)
            load_stage_body(st0 + stg2 * GEMM_STAGE, A, B,
                            tm, tn, (c + 2) * 64, K, tid);
        cp_commit();

        uint32_t sa = st0 + stg * GEMM_STAGE;
        uint32_t sbb = sa + 16384;

        // register double-buffered fragments across the 4 k16 chunks
        uint32_t aF[2][16], bF[2][8];
        ldfragA(aF[0], sa + aOff);
        ldfragB(bF[0], sbb + bOff);

        #pragma unroll
        for (int kc = 0; kc < 4; kc++) {
            int cur = kc & 1, nxt = cur ^ 1;
            if (kc < 3) {
                ldfragA(aF[nxt], sa + (kc + 1) * 4096 + aOff);
                ldfragB(bF[nxt], sbb + (kc + 1) * 4096 + bOff);
            }
            #pragma unroll
            for (int mi = 0; mi < 4; mi++)
                #pragma unroll
                for (int ni = 0; ni < 4; ni++)
                    mma16816(acc[mi][ni], &aF[cur][mi * 4], &bF[cur][ni * 2]);
        }

        stg  = (stg  + 1 == GEMM_NSTAGE) ? 0 : stg + 1;
        stg2 = (stg2 + 1 == GEMM_NSTAGE) ? 0 : stg2 + 1;
    }

    int r0 = (lane >> 2);
    int c0 = (lane & 3) * 2;
    #pragma unroll
    for (int mi = 0; mi < 4; mi++) {
        long row = tm + wm + mi * 16 + r0;
        #pragma unroll
        for (int ni = 0; ni < 4; ni++) {
            long col = tn + wn + ni * 8 + c0;
            *(float2*)&C[row * (long)Nn + col] =
                make_float2(acc[mi][ni][0], acc[mi][ni][1]);
            *(float2*)&C[(row + 8) * (long)Nn + col] =
                make_float2(acc[mi][ni][2], acc[mi][ni][3]);
        }
    }
}

// ---------------- RoPE + head-major fp16 hi/lo split ----------------
__global__ void rope_split() {
    int idx = blockIdx.x * blockDim.x + threadIdx.x;
    if (idx >= N_TOK * 64) return;
    int d = idx & 63;
    int m = idx >> 6;
    int n = m & (NSEQ - 1);
    int b = m >> 11;

    double inv = exp(-(double)d * (9.210340371976184 / 64.0));
    double ang = (double)n * inv;
    const double TWO_PI = 6.283185307179586476925286766559;
    double w = ang - floor(ang / TWO_PI) * TWO_PI;
    float c = cosf((float)w);
    float s = sinf((float)w);
    const float scale = 0.088388347648318447f;   // 1/sqrt(128)

    const float* base = g_qkv + (long)m * EQKV;
    #pragma unroll
    for (int h = 0; h < NHEADS; h++) {
        const float* q = base + h * HDIM;
        const float* k = q + INNERD;
        const float* v = k + INNERD;
        float q1 = q[d], q2 = q[d + 64];
        float k1 = k[d], k2 = k[d + 64];
        float v1 = v[d], v2 = v[d + 64];
        float qr1 = (q1 * c - q2 * s) * scale;
        float qr2 = (q2 * c + q1 * s) * scale;
        float kr1 = k1 * c - k2 * s;
        float kr2 = k2 * c + k1 * s;

        long o = ((long)(b * NHEADS + h) * NSEQ + n) * HDIM;
        __half hh, ll;
        splith(qr1, hh, ll); g_qh[o + d] = hh;      g_ql[o + d] = ll;
        splith(qr2, hh, ll); g_qh[o + d + 64] = hh; g_ql[o + d + 64] = ll;
        splith(kr1, hh, ll); g_kh[o + d] = hh;      g_kl[o + d] = ll;
        splith(kr2, hh, ll); g_kh[o + d + 64] = hh; g_kl[o + d + 64] = ll;
        splith(v1,  hh, ll); g_vh[o + d] = hh;      g_vl[o + d] = ll;
        splith(v2,  hh, ll); g_vh[o + d + 64] = hh; g_vl[o + d + 64] = ll;
    }
}

// ---------------- HMMA flash attention (3-term hi/lo) ----------------
#define AQ 128
#define SQ_BYTES 32768
#define SK_BYTES 16384
#define ASTAGE   (4 * SK_BYTES)                     // 64KB
#define ATTN_SMEM_BYTES (2 * SQ_BYTES + 2 * ASTAGE) // 192KB

__device__ __forceinline__ void load_q(uint32_t sQh, uint32_t sQl,
                                       const __half* qh, const __half* ql, int tid) {
    #pragma unroll
    for (int it = 0; it < 16; it++) {
        int s = tid + it * 256;
        int mat = s >> 11;
        int r = (s >> 4) & 127;
        int q = s & 15;
        uint32_t dst = (mat ? sQl : sQh) + (q >> 1) * 4096 + r * 32 + (q & 1) * 16;
        cp16(dst, (mat ? ql : qh) + r * 128 + q * 8);
    }
}

__device__ __forceinline__ void load_kv(uint32_t st,
                                        const __half* kh, const __half* kl,
                                        const __half* vh, const __half* vl, int tid) {
    #pragma unroll
    for (int it = 0; it < 16; it++) {
        int s = tid + it * 256;
        int mat = s >> 10;
        int r = (s >> 4) & 63;
        int q = s & 15;
        const __half* src = (mat == 0) ? kh : (mat == 1) ? kl : (mat == 2) ? vh : vl;
        uint32_t dst = st + mat * SK_BYTES + (q >> 1) * 2048 + r * 32 + (q & 1) * 16;
        cp16(dst, src + r * 128 + q * 8);
    }
}

__global__ __launch_bounds__(256, 1) void attn_tc() {
    extern __shared__ char dynsmem[];
    uint32_t sb  = smem_u32(dynsmem);
    uint32_t sQh = sb;
    uint32_t sQl = sb + SQ_BYTES;
    uint32_t st0 = sb + 2 * SQ_BYTES;

    int tid  = threadIdx.x;
    int lane = tid & 31;
    int wid  = tid >> 5;
    int qb   = blockIdx.x;
    int h    = blockIdx.y;
    int b    = blockIdx.z;
    int qs   = qb * AQ;

    long hb = (long)(b * NHEADS + h) * NSEQ;
    const __half* qhg = g_qh + (hb + qs) * HDIM;
    const __half* qlg = g_ql + (hb + qs) * HDIM;

    int kt0 = (qs >= WINDOW) ? ((qs - WINDOW + 1) >> 6) : 0;
    int kt1 = (qs + AQ - 1) >> 6;

    load_q(sQh, sQl, qhg, qlg, tid);
    {
        int ks = kt0 * 64;
        load_kv(st0, g_kh + (hb + ks) * HDIM, g_kl + (hb + ks) * HDIM,
                g_vh + (hb + ks) * HDIM, g_vl + (hb + ks) * HDIM, tid);
    }
    cp_commit();
    if (kt0 + 1 <= kt1) {
        int ks = (kt0 + 1) * 64;
        load_kv(st0 + ASTAGE, g_kh + (hb + ks) * HDIM, g_kl + (hb + ks) * HDIM,
                g_vh + (hb + ks) * HDIM, g_vl + (hb + ks) * HDIM, tid);
    }
    cp_commit();

    int qw = qs + wid * 16;
    int r0 = lane >> 2;
    int cb = (lane & 3) * 2;

    uint32_t qOff = (uint32_t)((wid * 16 + (lane & 15)) * 32 + (lane >> 4) * 16);
    uint32_t kRow = (uint32_t)((lane & 7) + ((lane >> 4) << 3));
    uint32_t kHlf = (uint32_t)(((lane >> 3) & 1) * 16);
    uint32_t vOff = (uint32_t)((lane & 15) * 32 + (lane >> 4) * 16);

    float mrow[2], lrow[2];
    float oacc[16][4];
    mrow[0] = mrow[1] = -1e30f;
    lrow[0] = lrow[1] = 0.f;
    #pragma unroll
    for (int nt = 0; nt < 16; nt++)
        #pragma unroll
        for (int q = 0; q < 4; q++) oacc[nt][q] = 0.f;

    for (int kt = kt0; kt <= kt1; kt++) {
        int st = (kt - kt0) & 1;
        asm volatile("cp.async.wait_group 1;" ::: "memory");
        __syncthreads();

        int ks = kt * 64;
        uint32_t S  = st0 + st * ASTAGE;
        uint32_t kh_ = S, kl_ = S + SK_BYTES;
        uint32_t vh_ = S + 2 * SK_BYTES, vl_ = S + 3 * SK_BYTES;

        bool active = (ks <= qw + 15) && (ks + 63 > qw - WINDOW);

        if (active) {
            float sacc[8][4];
            #pragma unroll
            for (int nt = 0; nt < 8; nt++)
                #pragma unroll
                for (int q = 0; q < 4; q++) sacc[nt][q] = 0.f;

            #pragma unroll
            for (int c = 0; c < 8; c++) {
                uint32_t aH[4], aL[4];
                ldsm_x4(aH, sQh + c * 4096 + qOff);
                ldsm_x4(aL, sQl + c * 4096 + qOff);
                #pragma unroll
                for (int p = 0; p < 4; p++) {
                    uint32_t addr = (p * 16 + kRow) * 32 + kHlf + c * 2048;
                    uint32_t bh[4], bl[4];
                    ldsm_x4(bh, kh_ + addr);
                    ldsm_x4(bl, kl_ + addr);
                    mma16816(sacc[2 * p],     aH, bh);
                    mma16816(sacc[2 * p],     aH, bl);
                    mma16816(sacc[2 * p],     aL, bh);
                    mma16816(sacc[2 * p + 1], aH, bh + 2);
                    mma16816(sacc[2 * p + 1], aH, bl + 2);
                    mma16816(sacc[2 * p + 1], aL, bh + 2);
                }
            }

            #pragma unroll
            for (int hf = 0; hf < 2; hf++) {
                int qi = qw + r0 + hf * 8;
                float mx = -1e30f;
                #pragma unroll
                for (int nt = 0; nt < 8; nt++) {
                    int kj0 = ks + nt * 8 + cb;
                    float v0 = sacc[nt][hf * 2], v1 = sacc[nt][hf * 2 + 1];
                    if (kj0 > qi || kj0 <= qi - WINDOW) v0 = -1e30f;
                    if (kj0 + 1 > qi || kj0 + 1 <= qi - WINDOW) v1 = -1e30f;
                    sacc[nt][hf * 2] = v0; sacc[nt][hf * 2 + 1] = v1;
                    mx = fmaxf(mx, fmaxf(v0, v1));
                }
                mx = fmaxf(mx, __shfl_xor_sync(0xffffffffu, mx, 1));
                mx = fmaxf(mx, __shfl_xor_sync(0xffffffffu, mx, 2));
                float mnew  = fmaxf(mrow[hf], mx);
                float alpha = __expf(mrow[hf] - mnew);
                mrow[hf] = mnew;

                float rs = 0.f;
                #pragma unroll
                for (int nt = 0; nt < 8; nt++) {
                    float v0 = sacc[nt][hf * 2], v1 = sacc[nt][hf * 2 + 1];
                    float p0 = (v0 < -1e29f) ? 0.f : __expf(v0 - mnew);
                    float p1 = (v1 < -1e29f) ? 0.f : __expf(v1 - mnew);
                    sacc[nt][hf * 2] = p0; sacc[nt][hf * 2 + 1] = p1;
                    rs += p0 + p1;
                }
                rs += __shfl_xor_sync(0xffffffffu, rs, 1);
                rs += __shfl_xor_sync(0xffffffffu, rs, 2);
                lrow[hf] = lrow[hf] * alpha + rs;

                #pragma unroll
                for (int nt = 0; nt < 16; nt++) {
                    oacc[nt][hf * 2]     *= alpha;
                    oacc[nt][hf * 2 + 1] *= alpha;
                }
            }

            uint32_t aPh[4][4], aPl[4][4];
            #pragma unroll
            for (int t = 0; t < 4; t++) {
                #pragma unroll
                for (int j = 0; j < 4; j++) {
                    int nt = 2 * t + (j >> 1);
                    int q0 = (j & 1) * 2;
                    __half h0, l0, h1, l1;
                    splith(sacc[nt][q0],     h0, l0);
                    splith(sacc[nt][q0 + 1], h1, l1);
                    aPh[t][j] = pack2(h0, h1);
                    aPl[t][j] = pack2(l0, l1);
                }
            }

            #pragma unroll
            for (int t = 0; t < 4; t++) {
                #pragma unroll
                for (int cc = 0; cc < 8; cc++) {
                    uint32_t addr = cc * 2048 + t * 512 + vOff;
                    uint32_t vh[4], vl[4];
                    ldsm_x4t(vh, vh_ + addr);
                    ldsm_x4t(vl, vl_ + addr);
                    mma16816(oacc[2 * cc],     aPh[t], vh);
                    mma16816(oacc[2 * cc],     aPh[t], vl);
                    mma16816(oacc[2 * cc],     aPl[t], vh);
                    mma16816(oacc[2 * cc + 1], aPh[t], vh + 2);
                    mma16816(oacc[2 * cc + 1], aPh[t], vl + 2);
                    mma16816(oacc[2 * cc + 1], aPl[t], vh + 2);
                }
            }
        }

        __syncthreads();
        if (kt + 2 <= kt1) {
            int ks2 = (kt + 2) * 64;
            load_kv(st0 + st * ASTAGE,
                    g_kh + (hb + ks2) * HDIM, g_kl + (hb + ks2) * HDIM,
                    g_vh + (hb + ks2) * HDIM, g_vl + (hb + ks2) * HDIM, tid);
        }
        cp_commit();
    }

    #pragma unroll
    for (int hf = 0; hf < 2; hf++) {
        float inv = 1.0f / lrow[hf];
        long tok = (long)b * NSEQ + qw + r0 + hf * 8;
        #pragma unroll
        for (int nt = 0; nt < 16; nt++) {
            int col = h * HDIM + nt * 8 + cb;
            float o0 = oacc[nt][hf * 2] * inv;
            float o1 = oacc[nt][hf * 2 + 1] * inv;
            *(__half2*)&g_ah[tok * INNERD + col] =
                __halves2half2(__float2half_rn(o0), __float2half_rn(o1));
        }
    }
}

// ---------------- launch ----------------
extern "C" void kernel_launch(void* const* d_in, const int* in_sizes, int n_in,
                              void* d_out, int out_size) {
    const float* x     = (const float*)d_in[0];
    const float* w_qkv = (const float*)d_in[1];
    const float* w_o   = (const float*)d_in[2];
    float* y = (float*)d_out;

    float* qkv = nullptr;
    __half *xh, *wq, *wo, *ah;
    cudaGetSymbolAddress((void**)&qkv, g_qkv);
    cudaGetSymbolAddress((void**)&xh,  g_xh);
    cudaGetSymbolAddress((void**)&wq,  g_wq);
    cudaGetSymbolAddress((void**)&wo,  g_wo);
    cudaGetSymbolAddress((void**)&ah,  g_ah);

    cudaFuncSetAttribute(gemm_tc,
                         cudaFuncAttributeMaxDynamicSharedMemorySize,
                         GEMM_SMEM_BYTES);
    cudaFuncSetAttribute(attn_tc,
                         cudaFuncAttributeMaxDynamicSharedMemorySize,
                         ATTN_SMEM_BYTES);

    // 1) round operands to fp16
    {
        int n4 = (N_TOK * DMODEL) / 4;
        conv_f16<<<n4 / 256, 256>>>((const float4*)x, (__half2*)xh, n4);
    }
    {
        int n4 = (EQKV * DMODEL) / 4;
        conv_f16<<<n4 / 256, 256>>>((const float4*)w_qkv, (__half2*)wq, n4);
    }
    {
        int n4 = (DMODEL * INNERD) / 4;
        conv_f16<<<n4 / 256, 256>>>((const float4*)w_o, (__half2*)wo, n4);
    }

    // 2) QKV projection -> g_qkv fp32
    gemm_tc<<<dim3(EQKV / 128, N_TOK / 128), 256, GEMM_SMEM_BYTES>>>(
        xh, wq, qkv, EQKV, DMODEL);

    // 3) RoPE + head-major fp16 hi/lo split
    rope_split<<<(N_TOK * 64) / 256, 256>>>();

    // 4) HMMA flash attention -> g_ah (fp16, [tok][inner])
    attn_tc<<<dim3(NSEQ / AQ, NHEADS, BATCH), 256, ATTN_SMEM_BYTES>>>();

    // 5) output projection -> y
    gemm_tc<<<dim3(DMODEL / 128, N_TOK / 128), 256, GEMM_SMEM_BYTES>>>(
        ah, wo, y, DMODEL, INNERD);
}

// round 15
// speedup vs baseline: 1.5264x; 1.0254x over previous
#include <cuda_runtime.h>
#include <cuda_fp16.h>
#include <cstdint>

#define BATCH   2
#define NSEQ    2048
#define DMODEL  2048
#define INNERD  2048
#define EQKV    6144
#define NHEADS  16
#define HDIM    128
#define WINDOW  512
#define N_TOK   (BATCH * NSEQ)   // 4096
#define NHTOT   (BATCH * NHEADS * NSEQ * HDIM)   // 8.4M

typedef unsigned long long ull;

// ---------------- scratch (__device__ globals) ----------------
__device__ float g_qkv[N_TOK * EQKV];                    // fp32 qkv
__device__ __align__(16) __half g_xh[N_TOK * DMODEL];    // x fp16
__device__ __align__(16) __half g_wq[EQKV * DMODEL];     // w_qkv fp16
__device__ __align__(16) __half g_wo[DMODEL * INNERD];   // w_o fp16
__device__ __align__(16) __half g_ah[N_TOK * INNERD];    // attn out fp16
// head-major roped q/k/v, fp16 hi/lo (attention stays 3-term):
__device__ __align__(16) __half g_qh[NHTOT];
__device__ __align__(16) __half g_ql[NHTOT];
__device__ __align__(16) __half g_kh[NHTOT];
__device__ __align__(16) __half g_kl[NHTOT];
__device__ __align__(16) __half g_vh[NHTOT];
__device__ __align__(16) __half g_vl[NHTOT];

// ---------------- PTX helpers (baseline ISA only) ----------------
__device__ __forceinline__ uint32_t smem_u32(const void* p) {
    uint32_t a;
    asm("{ .reg .u64 t; cvta.to.shared.u64 t, %1; cvt.u32.u64 %0, t; }"
        : "=r"(a) : "l"(p));
    return a;
}
__device__ __forceinline__ void cp16(uint32_t dst, const void* src) {
    asm volatile("cp.async.cg.shared.global [%0], [%1], 16;" :: "r"(dst), "l"(src));
}
__device__ __forceinline__ void cp_commit() {
    asm volatile("cp.async.commit_group;" ::: "memory");
}
__device__ __forceinline__ void ldsm_x4(uint32_t* r, uint32_t addr) {
    asm volatile("ldmatrix.sync.aligned.m8n8.x4.shared.b16 {%0,%1,%2,%3}, [%4];"
                 : "=r"(r[0]), "=r"(r[1]), "=r"(r[2]), "=r"(r[3]) : "r"(addr));
}
__device__ __forceinline__ void ldsm_x4t(uint32_t* r, uint32_t addr) {
    asm volatile("ldmatrix.sync.aligned.m8n8.x4.trans.shared.b16 {%0,%1,%2,%3}, [%4];"
                 : "=r"(r[0]), "=r"(r[1]), "=r"(r[2]), "=r"(r[3]) : "r"(addr));
}
__device__ __forceinline__ void mma16816(float* c, const uint32_t* a, const uint32_t* b) {
    asm volatile("mma.sync.aligned.m16n8k16.row.col.f32.f16.f16.f32 "
                 "{%0,%1,%2,%3}, {%4,%5,%6,%7}, {%8,%9}, {%0,%1,%2,%3};"
                 : "+f"(c[0]), "+f"(c[1]), "+f"(c[2]), "+f"(c[3])
                 : "r"(a[0]), "r"(a[1]), "r"(a[2]), "r"(a[3]),
                   "r"(b[0]), "r"(b[1]));
}
__device__ __forceinline__ void splith(float x, __half& h, __half& l) {
    h = __float2half_rn(x);
    l = __float2half_rn(x - __half2float(h));
}
__device__ __forceinline__ uint32_t pack2(__half a, __half b) {
    __half2 t = __halves2half2(a, b);
    return *(uint32_t*)&t;
}

// ---------------- fp32 -> fp16 round ----------------
__global__ void conv_f16(const float4* __restrict__ in,
                         __half2* __restrict__ out, int n4) {
    int i = blockIdx.x * blockDim.x + threadIdx.x;
    if (i >= n4) return;
    float4 v = in[i];
    out[i * 2]     = __halves2half2(__float2half_rn(v.x), __float2half_rn(v.y));
    out[i * 2 + 1] = __halves2half2(__float2half_rn(v.z), __float2half_rn(v.w));
}

// ---------------- mma.sync fp16 NT GEMM (CTA 256x128, warp 64x64) ----------
// C[M,N] = A[M,K] * B[N,K]^T in fp32.
// 256 threads, 8 warps = 4m x 2n, warp tile 64x64 (acc 128 regs/thread).
// BK=64, 4 stages x 48KB = 192KB smem, wait_group 2.
// SMEM stage: A at +0:     [kc0..3][row 0..255][32B] (kc*8192 + r*32)
//             B at +32768: [kc0..3][row 0..127][32B] (kc*4096 + r*32)
#define GEMM_STAGE   49152
#define GEMM_NSTAGE  4
#define GEMM_SMEM_BYTES (GEMM_NSTAGE * GEMM_STAGE)   // 196608

__device__ __forceinline__ void load_stage_body(
    uint32_t st, const __half* __restrict__ A, const __half* __restrict__ B,
    long tm, long tn, int k0, int K, int tid)
{
    #pragma unroll
    for (int it = 0; it < 12; it++) {
        int s = tid + it * 256;          // 0..3071
        uint32_t dst; const __half* src; long row;
        if (s < 2048) {                  // A: 256 rows x 8 quads
            int r = s >> 3;
            int q = s & 7;
            src = A; row = tm + r;
            dst = st + (q >> 1) * 8192 + r * 32 + (q & 1) * 16;
            cp16(dst, src + row * (long)K + k0 + q * 8);
        } else {                         // B: 128 rows x 8 quads
            int s2 = s - 2048;
            int r = s2 >> 3;
            int q = s2 & 7;
            src = B; row = tn + r;
            dst = st + 32768 + (q >> 1) * 4096 + r * 32 + (q & 1) * 16;
            cp16(dst, src + row * (long)K + k0 + q * 8);
        }
    }
}

__global__ __launch_bounds__(256, 1) void gemm_tc(
    const __half* __restrict__ A, const __half* __restrict__ B,
    float* __restrict__ C, int Nn, int K)
{
    extern __shared__ char dynsmem[];
    uint32_t st0 = smem_u32(dynsmem);

    int tid  = threadIdx.x;
    int lane = tid & 31;
    int wid  = tid >> 5;
    int wm   = (wid >> 1) * 64;      // warp m offset: 0,64,128,192
    int wn   = (wid & 1) * 64;       // warp n offset: 0,64

    long tm = (long)blockIdx.y * 256;
    long tn = (long)blockIdx.x * 128;
    int NC = K / 64;

    uint32_t aOff = (uint32_t)((wm + (lane & 15)) * 32 + (lane >> 4) * 16);
    uint32_t bRow = (uint32_t)((lane & 7) + ((lane >> 4) << 3));
    uint32_t bHlf = (uint32_t)(((lane >> 3) & 1) * 16);

    float acc[4][8][4];
    #pragma unroll
    for (int mi = 0; mi < 4; mi++)
        #pragma unroll
        for (int ni = 0; ni < 8; ni++)
            #pragma unroll
            for (int q = 0; q < 4; q++) acc[mi][ni][q] = 0.f;

    load_stage_body(st0, A, B, tm, tn, 0, K, tid);
    cp_commit();
    load_stage_body(st0 + GEMM_STAGE, A, B, tm, tn, 64, K, tid);
    cp_commit();
    load_stage_body(st0 + 2 * GEMM_STAGE, A, B, tm, tn, 128, K, tid);
    cp_commit();

    int stg = 0, stg3 = 3;
    for (int c = 0; c < NC; c++) {
        asm volatile("cp.async.wait_group 2;" ::: "memory");
        __syncthreads();

        if (c + 3 < NC)
            load_stage_body(st0 + stg3 * GEMM_STAGE, A, B,
                            tm, tn, (c + 3) * 64, K, tid);
        cp_commit();

        uint32_t sa = st0 + stg * GEMM_STAGE;
        uint32_t sbb = sa + 32768;

        #pragma unroll
        for (int kc = 0; kc < 4; kc++) {
            uint32_t aB = sa + kc * 8192 + aOff;
            uint32_t bB = sbb + kc * 4096;

            uint32_t aF[4][4], bF[4][4];
            #pragma unroll
            for (int mi = 0; mi < 4; mi++)
                ldsm_x4(aF[mi], aB + mi * 512);
            #pragma unroll
            for (int p = 0; p < 4; p++)
                ldsm_x4(bF[p], bB + (wn + p * 16 + bRow) * 32 + bHlf);

            #pragma unroll
            for (int mi = 0; mi < 4; mi++)
                #pragma unroll
                for (int p = 0; p < 4; p++) {
                    mma16816(acc[mi][2 * p],     aF[mi], bF[p]);
                    mma16816(acc[mi][2 * p + 1], aF[mi], bF[p] + 2);
                }
        }

        stg  = (stg  + 1 == GEMM_NSTAGE) ? 0 : stg + 1;
        stg3 = (stg3 + 1 == GEMM_NSTAGE) ? 0 : stg3 + 1;
    }

    int r0 = (lane >> 2);
    int c0 = (lane & 3) * 2;
    #pragma unroll
    for (int mi = 0; mi < 4; mi++) {
        long row = tm + wm + mi * 16 + r0;
        #pragma unroll
        for (int ni = 0; ni < 8; ni++) {
            long col = tn + wn + ni * 8 + c0;
            *(float2*)&C[row * (long)Nn + col] =
                make_float2(acc[mi][ni][0], acc[mi][ni][1]);
            *(float2*)&C[(row + 8) * (long)Nn + col] =
                make_float2(acc[mi][ni][2], acc[mi][ni][3]);
        }
    }
}

// ---------------- RoPE + head-major fp16 hi/lo split ----------------
__global__ void rope_split() {
    int idx = blockIdx.x * blockDim.x + threadIdx.x;
    if (idx >= N_TOK * 64) return;
    int d = idx & 63;
    int m = idx >> 6;
    int n = m & (NSEQ - 1);
    int b = m >> 11;

    double inv = exp(-(double)d * (9.210340371976184 / 64.0));
    double ang = (double)n * inv;
    const double TWO_PI = 6.283185307179586476925286766559;
    double w = ang - floor(ang / TWO_PI) * TWO_PI;
    float c = cosf((float)w);
    float s = sinf((float)w);
    const float scale = 0.088388347648318447f;   // 1/sqrt(128)

    const float* base = g_qkv + (long)m * EQKV;
    #pragma unroll
    for (int h = 0; h < NHEADS; h++) {
        const float* q = base + h * HDIM;
        const float* k = q + INNERD;
        const float* v = k + INNERD;
        float q1 = q[d], q2 = q[d + 64];
        float k1 = k[d], k2 = k[d + 64];
        float v1 = v[d], v2 = v[d + 64];
        float qr1 = (q1 * c - q2 * s) * scale;
        float qr2 = (q2 * c + q1 * s) * scale;
        float kr1 = k1 * c - k2 * s;
        float kr2 = k2 * c + k1 * s;

        long o = ((long)(b * NHEADS + h) * NSEQ + n) * HDIM;
        __half hh, ll;
        splith(qr1, hh, ll); g_qh[o + d] = hh;      g_ql[o + d] = ll;
        splith(qr2, hh, ll); g_qh[o + d + 64] = hh; g_ql[o + d + 64] = ll;
        splith(kr1, hh, ll); g_kh[o + d] = hh;      g_kl[o + d] = ll;
        splith(kr2, hh, ll); g_kh[o + d + 64] = hh; g_kl[o + d + 64] = ll;
        splith(v1,  hh, ll); g_vh[o + d] = hh;      g_vl[o + d] = ll;
        splith(v2,  hh, ll); g_vh[o + d + 64] = hh; g_vl[o + d + 64] = ll;
    }
}

// ---------------- HMMA flash attention (3-term hi/lo, unchanged) ----------
#define AQ 128
#define SQ_BYTES 32768
#define SK_BYTES 16384
#define ASTAGE   (4 * SK_BYTES)                     // 64KB
#define ATTN_SMEM_BYTES (2 * SQ_BYTES + 2 * ASTAGE) // 192KB

__device__ __forceinline__ void ldsm_x2a(uint32_t* r, uint32_t addr) {
    asm volatile("ldmatrix.sync.aligned.m8n8.x2.shared.b16 {%0,%1}, [%2];"
                 : "=r"(r[0]), "=r"(r[1]) : "r"(addr));
}

__device__ __forceinline__ void load_q(uint32_t sQh, uint32_t sQl,
                                       const __half* qh, const __half* ql, int tid) {
    #pragma unroll
    for (int it = 0; it < 16; it++) {
        int s = tid + it * 256;
        int mat = s >> 11;
        int r = (s >> 4) & 127;
        int q = s & 15;
        uint32_t dst = (mat ? sQl : sQh) + (q >> 1) * 4096 + r * 32 + (q & 1) * 16;
        cp16(dst, (mat ? ql : qh) + r * 128 + q * 8);
    }
}

__device__ __forceinline__ void load_kv(uint32_t st,
                                        const __half* kh, const __half* kl,
                                        const __half* vh, const __half* vl, int tid) {
    #pragma unroll
    for (int it = 0; it < 16; it++) {
        int s = tid + it * 256;
        int mat = s >> 10;
        int r = (s >> 4) & 63;
        int q = s & 15;
        const __half* src = (mat == 0) ? kh : (mat == 1) ? kl : (mat == 2) ? vh : vl;
        uint32_t dst = st + mat * SK_BYTES + (q >> 1) * 2048 + r * 32 + (q & 1) * 16;
        cp16(dst, src + r * 128 + q * 8);
    }
}

__global__ __launch_bounds__(256, 1) void attn_tc() {
    extern __shared__ char dynsmem[];
    uint32_t sb  = smem_u32(dynsmem);
    uint32_t sQh = sb;
    uint32_t sQl = sb + SQ_BYTES;
    uint32_t st0 = sb + 2 * SQ_BYTES;

    int tid  = threadIdx.x;
    int lane = tid & 31;
    int wid  = tid >> 5;
    int qb   = blockIdx.x;
    int h    = blockIdx.y;
    int b    = blockIdx.z;
    int qs   = qb * AQ;

    long hb = (long)(b * NHEADS + h) * NSEQ;
    const __half* qhg = g_qh + (hb + qs) * HDIM;
    const __half* qlg = g_ql + (hb + qs) * HDIM;

    int kt0 = (qs >= WINDOW) ? ((qs - WINDOW + 1) >> 6) : 0;
    int kt1 = (qs + AQ - 1) >> 6;

    load_q(sQh, sQl, qhg, qlg, tid);
    {
        int ks = kt0 * 64;
        load_kv(st0, g_kh + (hb + ks) * HDIM, g_kl + (hb + ks) * HDIM,
                g_vh + (hb + ks) * HDIM, g_vl + (hb + ks) * HDIM, tid);
    }
    cp_commit();
    if (kt0 + 1 <= kt1) {
        int ks = (kt0 + 1) * 64;
        load_kv(st0 + ASTAGE, g_kh + (hb + ks) * HDIM, g_kl + (hb + ks) * HDIM,
                g_vh + (hb + ks) * HDIM, g_vl + (hb + ks) * HDIM, tid);
    }
    cp_commit();

    int qw = qs + wid * 16;
    int r0 = lane >> 2;
    int cb = (lane & 3) * 2;

    uint32_t qOff = (uint32_t)((wid * 16 + (lane & 15)) * 32 + (lane >> 4) * 16);
    uint32_t kRow = (uint32_t)((lane & 7) + ((lane >> 4) << 3));
    uint32_t kHlf = (uint32_t)(((lane >> 3) & 1) * 16);
    uint32_t vOff = (uint32_t)((lane & 15) * 32 + (lane >> 4) * 16);

    float mrow[2], lrow[2];
    float oacc[16][4];
    mrow[0] = mrow[1] = -1e30f;
    lrow[0] = lrow[1] = 0.f;
    #pragma unroll
    for (int nt = 0; nt < 16; nt++)
        #pragma unroll
        for (int q = 0; q < 4; q++) oacc[nt][q] = 0.f;

    for (int kt = kt0; kt <= kt1; kt++) {
        int st = (kt - kt0) & 1;
        asm volatile("cp.async.wait_group 1;" ::: "memory");
        __syncthreads();

        int ks = kt * 64;
        uint32_t S  = st0 + st * ASTAGE;
        uint32_t kh_ = S, kl_ = S + SK_BYTES;
        uint32_t vh_ = S + 2 * SK_BYTES, vl_ = S + 3 * SK_BYTES;

        bool active = (ks <= qw + 15) && (ks + 63 > qw - WINDOW);

        if (active) {
            float sacc[8][4];
            #pragma unroll
            for (int nt = 0; nt < 8; nt++)
                #pragma unroll
                for (int q = 0; q < 4; q++) sacc[nt][q] = 0.f;

            #pragma unroll
            for (int c = 0; c < 8; c++) {
                uint32_t aH[4], aL[4];
                ldsm_x4(aH, sQh + c * 4096 + qOff);
                ldsm_x4(aL, sQl + c * 4096 + qOff);
                #pragma unroll
                for (int p = 0; p < 4; p++) {
                    uint32_t addr = (p * 16 + kRow) * 32 + kHlf + c * 2048;
                    uint32_t bh[4], bl[4];
                    ldsm_x4(bh, kh_ + addr);
                    ldsm_x4(bl, kl_ + addr);
                    mma16816(sacc[2 * p],     aH, bh);
                    mma16816(sacc[2 * p],     aH, bl);
                    mma16816(sacc[2 * p],     aL, bh);
                    mma16816(sacc[2 * p + 1], aH, bh + 2);
                    mma16816(sacc[2 * p + 1], aH, bl + 2);
                    mma16816(sacc[2 * p + 1], aL, bh + 2);
                }
            }

            #pragma unroll
            for (int hf = 0; hf < 2; hf++) {
                int qi = qw + r0 + hf * 8;
                float mx = -1e30f;
                #pragma unroll
                for (int nt = 0; nt < 8; nt++) {
                    int kj0 = ks + nt * 8 + cb;
                    float v0 = sacc[nt][hf * 2], v1 = sacc[nt][hf * 2 + 1];
                    if (kj0 > qi || kj0 <= qi - WINDOW) v0 = -1e30f;
                    if (kj0 + 1 > qi || kj0 + 1 <= qi - WINDOW) v1 = -1e30f;
                    sacc[nt][hf * 2] = v0; sacc[nt][hf * 2 + 1] = v1;
                    mx = fmaxf(mx, fmaxf(v0, v1));
                }
                mx = fmaxf(mx, __shfl_xor_sync(0xffffffffu, mx, 1));
                mx = fmaxf(mx, __shfl_xor_sync(0xffffffffu, mx, 2));
                float mnew  = fmaxf(mrow[hf], mx);
                float alpha = __expf(mrow[hf] - mnew);
                mrow[hf] = mnew;

                float rs = 0.f;
                #pragma unroll
                for (int nt = 0; nt < 8; nt++) {
                    float v0 = sacc[nt][hf * 2], v1 = sacc[nt][hf * 2 + 1];
                    float p0 = (v0 < -1e29f) ? 0.f : __expf(v0 - mnew);
                    float p1 = (v1 < -1e29f) ? 0.f : __expf(v1 - mnew);
                    sacc[nt][hf * 2] = p0; sacc[nt][hf * 2 + 1] = p1;
                    rs += p0 + p1;
                }
                rs += __shfl_xor_sync(0xffffffffu, rs, 1);
                rs += __shfl_xor_sync(0xffffffffu, rs, 2);
                lrow[hf] = lrow[hf] * alpha + rs;

                #pragma unroll
                for (int nt = 0; nt < 16; nt++) {
                    oacc[nt][hf * 2]     *= alpha;
                    oacc[nt][hf * 2 + 1] *= alpha;
                }
            }

            uint32_t aPh[4][4], aPl[4][4];
            #pragma unroll
            for (int t = 0; t < 4; t++) {
                #pragma unroll
                for (int j = 0; j < 4; j++) {
                    int nt = 2 * t + (j >> 1);
                    int q0 = (j & 1) * 2;
                    __half h0, l0, h1, l1;
                    splith(sacc[nt][q0],     h0, l0);
                    splith(sacc[nt][q0 + 1], h1, l1);
                    aPh[t][j] = pack2(h0, h1);
                    aPl[t][j] = pack2(l0, l1);
                }
            }

            #pragma unroll
            for (int t = 0; t < 4; t++) {
                #pragma unroll
                for (int cc = 0; cc < 8; cc++) {
                    uint32_t addr = cc * 2048 + t * 512 + vOff;
                    uint32_t vh[4], vl[4];
                    ldsm_x4t(vh, vh_ + addr);
                    ldsm_x4t(vl, vl_ + addr);
                    mma16816(oacc[2 * cc],     aPh[t], vh);
                    mma16816(oacc[2 * cc],     aPh[t], vl);
                    mma16816(oacc[2 * cc],     aPl[t], vh);
                    mma16816(oacc[2 * cc + 1], aPh[t], vh + 2);
                    mma16816(oacc[2 * cc + 1], aPh[t], vl + 2);
                    mma16816(oacc[2 * cc + 1], aPl[t], vh + 2);
                }
            }
        }

        __syncthreads();
        if (kt + 2 <= kt1) {
            int ks2 = (kt + 2) * 64;
            load_kv(st0 + st * ASTAGE,
                    g_kh + (hb + ks2) * HDIM, g_kl + (hb + ks2) * HDIM,
                    g_vh + (hb + ks2) * HDIM, g_vl + (hb + ks2) * HDIM, tid);
        }
        cp_commit();
    }

    #pragma unroll
    for (int hf = 0; hf < 2; hf++) {
        float inv = 1.0f / lrow[hf];
        long tok = (long)b * NSEQ + qw + r0 + hf * 8;
        #pragma unroll
        for (int nt = 0; nt < 16; nt++) {
            int col = h * HDIM + nt * 8 + cb;
            float o0 = oacc[nt][hf * 2] * inv;
            float o1 = oacc[nt][hf * 2 + 1] * inv;
            *(__half2*)&g_ah[tok * INNERD + col] =
                __halves2half2(__float2half_rn(o0), __float2half_rn(o1));
        }
    }
}

// ---------------- launch ----------------
extern "C" void kernel_launch(void* const* d_in, const int* in_sizes, int n_in,
                              void* d_out, int out_size) {
    const float* x     = (const float*)d_in[0];
    const float* w_qkv = (const float*)d_in[1];
    const float* w_o   = (const float*)d_in[2];
    float* y = (float*)d_out;

    float* qkv = nullptr;
    __half *xh, *wq, *wo, *ah;
    cudaGetSymbolAddress((void**)&qkv, g_qkv);
    cudaGetSymbolAddress((void**)&xh,  g_xh);
    cudaGetSymbolAddress((void**)&wq,  g_wq);
    cudaGetSymbolAddress((void**)&wo,  g_wo);
    cudaGetSymbolAddress((void**)&ah,  g_ah);

    cudaFuncSetAttribute(gemm_tc,
                         cudaFuncAttributeMaxDynamicSharedMemorySize,
                         GEMM_SMEM_BYTES);
    cudaFuncSetAttribute(attn_tc,
                         cudaFuncAttributeMaxDynamicSharedMemorySize,
                         ATTN_SMEM_BYTES);

    // 1) round operands to fp16
    {
        int n4 = (N_TOK * DMODEL) / 4;
        conv_f16<<<n4 / 256, 256>>>((const float4*)x, (__half2*)xh, n4);
    }
    {
        int n4 = (EQKV * DMODEL) / 4;
        conv_f16<<<n4 / 256, 256>>>((const float4*)w_qkv, (__half2*)wq, n4);
    }
    {
        int n4 = (DMODEL * INNERD) / 4;
        conv_f16<<<n4 / 256, 256>>>((const float4*)w_o, (__half2*)wo, n4);
    }

    // 2) QKV projection -> g_qkv fp32  (M=4096 x N=6144 x K=2048)
    gemm_tc<<<dim3(EQKV / 128, N_TOK / 256), 256, GEMM_SMEM_BYTES>>>(
        xh, wq, qkv, EQKV, DMODEL);

    // 3) RoPE + head-major fp16 hi/lo split
    rope_split<<<(N_TOK * 64) / 256, 256>>>();

    // 4) HMMA flash attention -> g_ah (fp16, [tok][inner])
    attn_tc<<<dim3(NSEQ / AQ, NHEADS, BATCH), 256, ATTN_SMEM_BYTES>>>();

    // 5) output projection -> y  (M=4096 x N=2048 x K=2048)
    gemm_tc<<<dim3(DMODEL / 128, N_TOK / 256), 256, GEMM_SMEM_BYTES>>>(
        ah, wo, y, DMODEL, INNERD);
}

// round 17
// speedup vs baseline: 1.7470x; 1.1445x over previous
#include <cuda_runtime.h>
#include <cuda_fp16.h>
#include <cstdint>

#define BATCH   2
#define NSEQ    2048
#define DMODEL  2048
#define INNERD  2048
#define EQKV    6144
#define NHEADS  16
#define HDIM    128
#define WINDOW  512
#define N_TOK   (BATCH * NSEQ)   // 4096
#define NHTOT   (BATCH * NHEADS * NSEQ * HDIM)   // 8.4M

typedef unsigned long long ull;

// ---------------- scratch (__device__ globals) ----------------
__device__ float g_qkv[N_TOK * EQKV];                    // fp32 qkv
__device__ __align__(16) __half g_xh[N_TOK * DMODEL];    // x fp16
__device__ __align__(16) __half g_wq[EQKV * DMODEL];     // w_qkv fp16
__device__ __align__(16) __half g_wo[DMODEL * INNERD];   // w_o fp16
__device__ __align__(16) __half g_ah[N_TOK * INNERD];    // attn out fp16
// head-major roped q/k/v, fp16 (single-term attention):
__device__ __align__(16) __half g_qh[NHTOT];
__device__ __align__(16) __half g_kh[NHTOT];
__device__ __align__(16) __half g_vh[NHTOT];

// ---------------- PTX helpers (baseline ISA only) ----------------
__device__ __forceinline__ uint32_t smem_u32(const void* p) {
    uint32_t a;
    asm("{ .reg .u64 t; cvta.to.shared.u64 t, %1; cvt.u32.u64 %0, t; }"
        : "=r"(a) : "l"(p));
    return a;
}
__device__ __forceinline__ void cp16(uint32_t dst, const void* src) {
    asm volatile("cp.async.cg.shared.global [%0], [%1], 16;" :: "r"(dst), "l"(src));
}
__device__ __forceinline__ void cp_commit() {
    asm volatile("cp.async.commit_group;" ::: "memory");
}
__device__ __forceinline__ void ldsm_x4(uint32_t* r, uint32_t addr) {
    asm volatile("ldmatrix.sync.aligned.m8n8.x4.shared.b16 {%0,%1,%2,%3}, [%4];"
                 : "=r"(r[0]), "=r"(r[1]), "=r"(r[2]), "=r"(r[3]) : "r"(addr));
}
__device__ __forceinline__ void ldsm_x4t(uint32_t* r, uint32_t addr) {
    asm volatile("ldmatrix.sync.aligned.m8n8.x4.trans.shared.b16 {%0,%1,%2,%3}, [%4];"
                 : "=r"(r[0]), "=r"(r[1]), "=r"(r[2]), "=r"(r[3]) : "r"(addr));
}
__device__ __forceinline__ void mma16816(float* c, const uint32_t* a, const uint32_t* b) {
    asm volatile("mma.sync.aligned.m16n8k16.row.col.f32.f16.f16.f32 "
                 "{%0,%1,%2,%3}, {%4,%5,%6,%7}, {%8,%9}, {%0,%1,%2,%3};"
                 : "+f"(c[0]), "+f"(c[1]), "+f"(c[2]), "+f"(c[3])
                 : "r"(a[0]), "r"(a[1]), "r"(a[2]), "r"(a[3]),
                   "r"(b[0]), "r"(b[1]));
}
__device__ __forceinline__ uint32_t pack2(__half a, __half b) {
    __half2 t = __halves2half2(a, b);
    return *(uint32_t*)&t;
}

// ---------------- fp32 -> fp16 round ----------------
__global__ void conv_f16(const float4* __restrict__ in,
                         __half2* __restrict__ out, int n4) {
    int i = blockIdx.x * blockDim.x + threadIdx.x;
    if (i >= n4) return;
    float4 v = in[i];
    out[i * 2]     = __halves2half2(__float2half_rn(v.x), __float2half_rn(v.y));
    out[i * 2 + 1] = __halves2half2(__float2half_rn(v.z), __float2half_rn(v.w));
}

// ---------------- mma.sync fp16 NT GEMM (CTA 256x128, warp 64x64) ----------
// (unchanged from R15 — best measured config)
#define GEMM_STAGE   49152
#define GEMM_NSTAGE  4
#define GEMM_SMEM_BYTES (GEMM_NSTAGE * GEMM_STAGE)   // 196608

__device__ __forceinline__ void load_stage_body(
    uint32_t st, const __half* __restrict__ A, const __half* __restrict__ B,
    long tm, long tn, int k0, int K, int tid)
{
    #pragma unroll
    for (int it = 0; it < 12; it++) {
        int s = tid + it * 256;          // 0..3071
        uint32_t dst; const __half* src; long row;
        if (s < 2048) {                  // A: 256 rows x 8 quads
            int r = s >> 3;
            int q = s & 7;
            src = A; row = tm + r;
            dst = st + (q >> 1) * 8192 + r * 32 + (q & 1) * 16;
            cp16(dst, src + row * (long)K + k0 + q * 8);
        } else {                         // B: 128 rows x 8 quads
            int s2 = s - 2048;
            int r = s2 >> 3;
            int q = s2 & 7;
            src = B; row = tn + r;
            dst = st + 32768 + (q >> 1) * 4096 + r * 32 + (q & 1) * 16;
            cp16(dst, src + row * (long)K + k0 + q * 8);
        }
    }
}

__global__ __launch_bounds__(256, 1) void gemm_tc(
    const __half* __restrict__ A, const __half* __restrict__ B,
    float* __restrict__ C, int Nn, int K)
{
    extern __shared__ char dynsmem[];
    uint32_t st0 = smem_u32(dynsmem);

    int tid  = threadIdx.x;
    int lane = tid & 31;
    int wid  = tid >> 5;
    int wm   = (wid >> 1) * 64;
    int wn   = (wid & 1) * 64;

    long tm = (long)blockIdx.y * 256;
    long tn = (long)blockIdx.x * 128;
    int NC = K / 64;

    uint32_t aOff = (uint32_t)((wm + (lane & 15)) * 32 + (lane >> 4) * 16);
    uint32_t bRow = (uint32_t)((lane & 7) + ((lane >> 4) << 3));
    uint32_t bHlf = (uint32_t)(((lane >> 3) & 1) * 16);

    float acc[4][8][4];
    #pragma unroll
    for (int mi = 0; mi < 4; mi++)
        #pragma unroll
        for (int ni = 0; ni < 8; ni++)
            #pragma unroll
            for (int q = 0; q < 4; q++) acc[mi][ni][q] = 0.f;

    load_stage_body(st0, A, B, tm, tn, 0, K, tid);
    cp_commit();
    load_stage_body(st0 + GEMM_STAGE, A, B, tm, tn, 64, K, tid);
    cp_commit();
    load_stage_body(st0 + 2 * GEMM_STAGE, A, B, tm, tn, 128, K, tid);
    cp_commit();

    int stg = 0, stg3 = 3;
    for (int c = 0; c < NC; c++) {
        asm volatile("cp.async.wait_group 2;" ::: "memory");
        __syncthreads();

        if (c + 3 < NC)
            load_stage_body(st0 + stg3 * GEMM_STAGE, A, B,
                            tm, tn, (c + 3) * 64, K, tid);
        cp_commit();

        uint32_t sa = st0 + stg * GEMM_STAGE;
        uint32_t sbb = sa + 32768;

        #pragma unroll
        for (int kc = 0; kc < 4; kc++) {
            uint32_t aB = sa + kc * 8192 + aOff;
            uint32_t bB = sbb + kc * 4096;

            uint32_t aF[4][4], bF[4][4];
            #pragma unroll
            for (int mi = 0; mi < 4; mi++)
                ldsm_x4(aF[mi], aB + mi * 512);
            #pragma unroll
            for (int p = 0; p < 4; p++)
                ldsm_x4(bF[p], bB + (wn + p * 16 + bRow) * 32 + bHlf);

            #pragma unroll
            for (int mi = 0; mi < 4; mi++)
                #pragma unroll
                for (int p = 0; p < 4; p++) {
                    mma16816(acc[mi][2 * p],     aF[mi], bF[p]);
                    mma16816(acc[mi][2 * p + 1], aF[mi], bF[p] + 2);
                }
        }

        stg  = (stg  + 1 == GEMM_NSTAGE) ? 0 : stg + 1;
        stg3 = (stg3 + 1 == GEMM_NSTAGE) ? 0 : stg3 + 1;
    }

    int r0 = (lane >> 2);
    int c0 = (lane & 3) * 2;
    #pragma unroll
    for (int mi = 0; mi < 4; mi++) {
        long row = tm + wm + mi * 16 + r0;
        #pragma unroll
        for (int ni = 0; ni < 8; ni++) {
            long col = tn + wn + ni * 8 + c0;
            *(float2*)&C[row * (long)Nn + col] =
                make_float2(acc[mi][ni][0], acc[mi][ni][1]);
            *(float2*)&C[(row + 8) * (long)Nn + col] =
                make_float2(acc[mi][ni][2], acc[mi][ni][3]);
        }
    }
}

// ---------------- RoPE + head-major fp16 round ----------------
__global__ void rope_split() {
    int idx = blockIdx.x * blockDim.x + threadIdx.x;
    if (idx >= N_TOK * 64) return;
    int d = idx & 63;
    int m = idx >> 6;
    int n = m & (NSEQ - 1);
    int b = m >> 11;

    double inv = exp(-(double)d * (9.210340371976184 / 64.0));
    double ang = (double)n * inv;
    const double TWO_PI = 6.283185307179586476925286766559;
    double w = ang - floor(ang / TWO_PI) * TWO_PI;
    float c = cosf((float)w);
    float s = sinf((float)w);
    const float scale = 0.088388347648318447f;   // 1/sqrt(128)

    const float* base = g_qkv + (long)m * EQKV;
    #pragma unroll
    for (int h = 0; h < NHEADS; h++) {
        const float* q = base + h * HDIM;
        const float* k = q + INNERD;
        const float* v = k + INNERD;
        float q1 = q[d], q2 = q[d + 64];
        float k1 = k[d], k2 = k[d + 64];
        float v1 = v[d], v2 = v[d + 64];
        float qr1 = (q1 * c - q2 * s) * scale;
        float qr2 = (q2 * c + q1 * s) * scale;
        float kr1 = k1 * c - k2 * s;
        float kr2 = k2 * c + k1 * s;

        long o = ((long)(b * NHEADS + h) * NSEQ + n) * HDIM;
        g_qh[o + d]      = __float2half_rn(qr1);
        g_qh[o + d + 64] = __float2half_rn(qr2);
        g_kh[o + d]      = __float2half_rn(kr1);
        g_kh[o + d + 64] = __float2half_rn(kr2);
        g_vh[o + d]      = __float2half_rn(v1);
        g_vh[o + d + 64] = __float2half_rn(v2);
    }
}

// ---------------- HMMA flash attention (single-term fp16) ----------------
// CTA = 128 queries x (head, batch). 256 threads, 8 warps; warp owns 16 rows.
// SMEM: sQ 32KB; per KV stage: K 16KB + V 16KB = 32KB; 2 stages. Total 96KB.
#define AQ 128
#define SQ_BYTES 32768
#define SK_BYTES 16384
#define ASTAGE   (2 * SK_BYTES)                     // 32KB
#define ATTN_SMEM_BYTES (SQ_BYTES + 2 * ASTAGE)     // 98304

__device__ __forceinline__ void load_q(uint32_t sQ,
                                       const __half* qh, int tid) {
    #pragma unroll
    for (int it = 0; it < 8; it++) {
        int s = tid + it * 256;          // 0..2047
        int r = (s >> 4) & 127;
        int q = s & 15;
        uint32_t dst = sQ + (q >> 1) * 4096 + r * 32 + (q & 1) * 16;
        cp16(dst, qh + r * 128 + q * 8);
    }
}

__device__ __forceinline__ void load_kv(uint32_t st,
                                        const __half* kh, const __half* vh, int tid) {
    #pragma unroll
    for (int it = 0; it < 8; it++) {
        int s = tid + it * 256;          // 0..2047
        int mat = s >> 10;               // 0=K, 1=V
        int r = (s >> 4) & 63;
        int q = s & 15;
        const __half* src = mat ? vh : kh;
        uint32_t dst = st + mat * SK_BYTES + (q >> 1) * 2048 + r * 32 + (q & 1) * 16;
        cp16(dst, src + r * 128 + q * 8);
    }
}

__global__ __launch_bounds__(256, 1) void attn_tc() {
    extern __shared__ char dynsmem[];
    uint32_t sb  = smem_u32(dynsmem);
    uint32_t sQ  = sb;
    uint32_t st0 = sb + SQ_BYTES;

    int tid  = threadIdx.x;
    int lane = tid & 31;
    int wid  = tid >> 5;
    int qb   = blockIdx.x;
    int h    = blockIdx.y;
    int b    = blockIdx.z;
    int qs   = qb * AQ;

    long hb = (long)(b * NHEADS + h) * NSEQ;
    const __half* qhg = g_qh + (hb + qs) * HDIM;

    int kt0 = (qs >= WINDOW) ? ((qs - WINDOW + 1) >> 6) : 0;
    int kt1 = (qs + AQ - 1) >> 6;

    load_q(sQ, qhg, tid);
    load_kv(st0, g_kh + (hb + kt0 * 64) * HDIM, g_vh + (hb + kt0 * 64) * HDIM, tid);
    cp_commit();
    if (kt0 + 1 <= kt1) {
        int ks = (kt0 + 1) * 64;
        load_kv(st0 + ASTAGE, g_kh + (hb + ks) * HDIM, g_vh + (hb + ks) * HDIM, tid);
    }
    cp_commit();

    int qw = qs + wid * 16;
    int r0 = lane >> 2;
    int cb = (lane & 3) * 2;

    uint32_t qOff = (uint32_t)((wid * 16 + (lane & 15)) * 32 + (lane >> 4) * 16);
    uint32_t kRow = (uint32_t)((lane & 7) + ((lane >> 4) << 3));
    uint32_t kHlf = (uint32_t)(((lane >> 3) & 1) * 16);
    uint32_t vOff = (uint32_t)((lane & 15) * 32 + (lane >> 4) * 16);

    float mrow[2], lrow[2];
    float oacc[16][4];
    mrow[0] = mrow[1] = -1e30f;
    lrow[0] = lrow[1] = 0.f;
    #pragma unroll
    for (int nt = 0; nt < 16; nt++)
        #pragma unroll
        for (int q = 0; q < 4; q++) oacc[nt][q] = 0.f;

    for (int kt = kt0; kt <= kt1; kt++) {
        int st = (kt - kt0) & 1;
        asm volatile("cp.async.wait_group 1;" ::: "memory");
        __syncthreads();

        int ks = kt * 64;
        uint32_t S  = st0 + st * ASTAGE;
        uint32_t kh_ = S, vh_ = S + SK_BYTES;

        bool active = (ks <= qw + 15) && (ks + 63 > qw - WINDOW);

        if (active) {
            // ---- S = Q K^T (single-term fp16) ----
            float sacc[8][4];
            #pragma unroll
            for (int nt = 0; nt < 8; nt++)
                #pragma unroll
                for (int q = 0; q < 4; q++) sacc[nt][q] = 0.f;

            #pragma unroll
            for (int c = 0; c < 8; c++) {
                uint32_t aH[4];
                ldsm_x4(aH, sQ + c * 4096 + qOff);
                #pragma unroll
                for (int p = 0; p < 4; p++) {
                    uint32_t addr = (p * 16 + kRow) * 32 + kHlf + c * 2048;
                    uint32_t bh[4];
                    ldsm_x4(bh, kh_ + addr);
                    mma16816(sacc[2 * p],     aH, bh);
                    mma16816(sacc[2 * p + 1], aH, bh + 2);
                }
            }

            // ---- mask + online softmax (warp-local rows) ----
            #pragma unroll
            for (int hf = 0; hf < 2; hf++) {
                int qi = qw + r0 + hf * 8;
                float mx = -1e30f;
                #pragma unroll
                for (int nt = 0; nt < 8; nt++) {
                    int kj0 = ks + nt * 8 + cb;
                    float v0 = sacc[nt][hf * 2], v1 = sacc[nt][hf * 2 + 1];
                    if (kj0 > qi || kj0 <= qi - WINDOW) v0 = -1e30f;
                    if (kj0 + 1 > qi || kj0 + 1 <= qi - WINDOW) v1 = -1e30f;
                    sacc[nt][hf * 2] = v0; sacc[nt][hf * 2 + 1] = v1;
                    mx = fmaxf(mx, fmaxf(v0, v1));
                }
                mx = fmaxf(mx, __shfl_xor_sync(0xffffffffu, mx, 1));
                mx = fmaxf(mx, __shfl_xor_sync(0xffffffffu, mx, 2));
                float mnew  = fmaxf(mrow[hf], mx);
                float alpha = __expf(mrow[hf] - mnew);
                mrow[hf] = mnew;

                float rs = 0.f;
                #pragma unroll
                for (int nt = 0; nt < 8; nt++) {
                    float v0 = sacc[nt][hf * 2], v1 = sacc[nt][hf * 2 + 1];
                    float p0 = (v0 < -1e29f) ? 0.f : __expf(v0 - mnew);
                    float p1 = (v1 < -1e29f) ? 0.f : __expf(v1 - mnew);
                    sacc[nt][hf * 2] = p0; sacc[nt][hf * 2 + 1] = p1;
                    rs += p0 + p1;
                }
                rs += __shfl_xor_sync(0xffffffffu, rs, 1);
                rs += __shfl_xor_sync(0xffffffffu, rs, 2);
                lrow[hf] = lrow[hf] * alpha + rs;

                #pragma unroll
                for (int nt = 0; nt < 16; nt++) {
                    oacc[nt][hf * 2]     *= alpha;
                    oacc[nt][hf * 2 + 1] *= alpha;
                }
            }

            // ---- P -> fp16 a-fragments ----
            uint32_t aP[4][4];
            #pragma unroll
            for (int t = 0; t < 4; t++) {
                #pragma unroll
                for (int j = 0; j < 4; j++) {
                    int nt = 2 * t + (j >> 1);
                    int q0 = (j & 1) * 2;
                    aP[t][j] = pack2(__float2half_rn(sacc[nt][q0]),
                                     __float2half_rn(sacc[nt][q0 + 1]));
                }
            }

            // ---- O += P V ----
            #pragma unroll
            for (int t = 0; t < 4; t++) {
                #pragma unroll
                for (int cc = 0; cc < 8; cc++) {
                    uint32_t addr = cc * 2048 + t * 512 + vOff;
                    uint32_t vh[4];
                    ldsm_x4t(vh, vh_ + addr);
                    mma16816(oacc[2 * cc],     aP[t], vh);
                    mma16816(oacc[2 * cc + 1], aP[t], vh + 2);
                }
            }
        }

        __syncthreads();
        if (kt + 2 <= kt1) {
            int ks2 = (kt + 2) * 64;
            load_kv(st0 + st * ASTAGE,
                    g_kh + (hb + ks2) * HDIM, g_vh + (hb + ks2) * HDIM, tid);
        }
        cp_commit();
    }

    // ---- epilogue: normalize, round to fp16 at [tok][h*128+d] ----
    #pragma unroll
    for (int hf = 0; hf < 2; hf++) {
        float inv = 1.0f / lrow[hf];
        long tok = (long)b * NSEQ + qw + r0 + hf * 8;
        #pragma unroll
        for (int nt = 0; nt < 16; nt++) {
            int col = h * HDIM + nt * 8 + cb;
            float o0 = oacc[nt][hf * 2] * inv;
            float o1 = oacc[nt][hf * 2 + 1] * inv;
            *(__half2*)&g_ah[tok * INNERD + col] =
                __halves2half2(__float2half_rn(o0), __float2half_rn(o1));
        }
    }
}

// ---------------- launch ----------------
extern "C" void kernel_launch(void* const* d_in, const int* in_sizes, int n_in,
                              void* d_out, int out_size) {
    const float* x     = (const float*)d_in[0];
    const float* w_qkv = (const float*)d_in[1];
    const float* w_o   = (const float*)d_in[2];
    float* y = (float*)d_out;

    float* qkv = nullptr;
    __half *xh, *wq, *wo, *ah;
    cudaGetSymbolAddress((void**)&qkv, g_qkv);
    cudaGetSymbolAddress((void**)&xh,  g_xh);
    cudaGetSymbolAddress((void**)&wq,  g_wq);
    cudaGetSymbolAddress((void**)&wo,  g_wo);
    cudaGetSymbolAddress((void**)&ah,  g_ah);

    cudaFuncSetAttribute(gemm_tc,
                         cudaFuncAttributeMaxDynamicSharedMemorySize,
                         GEMM_SMEM_BYTES);
    cudaFuncSetAttribute(attn_tc,
                         cudaFuncAttributeMaxDynamicSharedMemorySize,
                         ATTN_SMEM_BYTES);

    // 1) round operands to fp16
    {
        int n4 = (N_TOK * DMODEL) / 4;
        conv_f16<<<n4 / 256, 256>>>((const float4*)x, (__half2*)xh, n4);
    }
    {
        int n4 = (EQKV * DMODEL) / 4;
        conv_f16<<<n4 / 256, 256>>>((const float4*)w_qkv, (__half2*)wq, n4);
    }
    {
        int n4 = (DMODEL * INNERD) / 4;
        conv_f16<<<n4 / 256, 256>>>((const float4*)w_o, (__half2*)wo, n4);
    }

    // 2) QKV projection -> g_qkv fp32  (M=4096 x N=6144 x K=2048)
    gemm_tc<<<dim3(EQKV / 128, N_TOK / 256), 256, GEMM_SMEM_BYTES>>>(
        xh, wq, qkv, EQKV, DMODEL);

    // 3) RoPE + head-major fp16 round
    rope_split<<<(N_TOK * 64) / 256, 256>>>();

    // 4) HMMA flash attention (single-term fp16) -> g_ah
    attn_tc<<<dim3(NSEQ / AQ, NHEADS, BATCH), 256, ATTN_SMEM_BYTES>>>();

    // 5) output projection -> y  (M=4096 x N=2048 x K=2048)
    gemm_tc<<<dim3(DMODEL / 128, N_TOK / 256), 256, GEMM_SMEM_BYTES>>>(
        ah, wo, y, DMODEL, INNERD);
}